// round 1
// baseline (speedup 1.0000x reference)
#include <cuda_runtime.h>
#include <math.h>

#define V 50257
#define H 1024
#define S 2048
#define NB_LOG 6283   // ceil(V/8)

// out layout: [0,V) log_softmax | [V, V+H) context | [V+H, V+3H) hidden(h0,h1) | [V+3H, V+3H+S) attn
#define OUT_CTX  (V)
#define OUT_HID  (V + H)
#define OUT_ATTN (V + 3*H)

// ---------------- scratch (device globals; no allocations) ----------------
__device__ float g_x[2*H];        // [emb_row, last_context]
__device__ float g_h0[H];
__device__ float g_h1[H];
__device__ float g_v[H];          // Wa^T @ h1
__device__ float g_scores[S];
__device__ float g_attn[S];
__device__ float g_context[H];
__device__ float g_logits[V];
__device__ float g_pm[NB_LOG];    // per-block max
__device__ float g_ps[NB_LOG];    // per-block sum exp
__device__ float g_M, g_logS;

__device__ __forceinline__ float warp_sum(float v) {
    #pragma unroll
    for (int o = 16; o; o >>= 1) v += __shfl_down_sync(0xffffffffu, v, o);
    return v;
}
__device__ __forceinline__ float warp_max(float v) {
    #pragma unroll
    for (int o = 16; o; o >>= 1) v = fmaxf(v, __shfl_down_sync(0xffffffffu, v, o));
    return v;
}

// ---------------- K0: build x = [emb[word], last_context]; zero accumulators
__global__ void k0_build(const int* __restrict__ word,
                         const float* __restrict__ emb,
                         const float* __restrict__ last_ctx) {
    int t = threadIdx.x;                       // 1024 threads
    int wi = word[0];
    g_x[t]       = emb[(size_t)wi * H + t];
    g_x[H + t]   = last_ctx[t];
    g_v[t]       = 0.f;
    g_context[t] = 0.f;
}

// ---------------- K1/K2: GRU cell. block k computes h_new[k]. 256 threads.
__global__ void k_gru(const float* __restrict__ x, int xdim,
                      const float* __restrict__ hprev,
                      const float* __restrict__ Wih,
                      const float* __restrict__ Whh,
                      const float* __restrict__ bih,
                      const float* __restrict__ bhh,
                      float* __restrict__ hnew,
                      float* __restrict__ out_hidden) {
    const int k = blockIdx.x;                  // 0..H-1
    const int t = threadIdx.x;                 // 256
    float acc[6];
    #pragma unroll
    for (int g = 0; g < 6; g++) acc[g] = 0.f;

    const float4* x4 = (const float4*)x;
    const float4* h4 = (const float4*)hprev;
    const int xd4 = xdim >> 2;                 // 512 or 256
    #pragma unroll
    for (int g = 0; g < 3; g++) {
        const float4* w4 = (const float4*)(Wih + (size_t)(g * H + k) * xdim);
        float a = 0.f;
        for (int i = t; i < xd4; i += 256) {
            float4 w = w4[i], xv = x4[i];
            a += w.x*xv.x + w.y*xv.y + w.z*xv.z + w.w*xv.w;
        }
        acc[g] = a;
    }
    #pragma unroll
    for (int g = 0; g < 3; g++) {
        const float4* w4 = (const float4*)(Whh + (size_t)(g * H + k) * H);
        float a = 0.f;
        for (int i = t; i < (H >> 2); i += 256) {
            float4 w = w4[i], hv = h4[i];
            a += w.x*hv.x + w.y*hv.y + w.z*hv.z + w.w*hv.w;
        }
        acc[3 + g] = a;
    }

    __shared__ float red[6][8];
    int w = t >> 5, lane = t & 31;
    #pragma unroll
    for (int g = 0; g < 6; g++) {
        float s = warp_sum(acc[g]);
        if (lane == 0) red[g][w] = s;
    }
    __syncthreads();
    if (t == 0) {
        float s[6];
        #pragma unroll
        for (int g = 0; g < 6; g++) {
            float a = 0.f;
            #pragma unroll
            for (int j = 0; j < 8; j++) a += red[g][j];
            s[g] = a;
        }
        float ir = s[0] + bih[k],       hr = s[3] + bhh[k];
        float iz = s[1] + bih[H + k],   hz = s[4] + bhh[H + k];
        float in_= s[2] + bih[2*H + k], hn = s[5] + bhh[2*H + k];
        float r = 1.f / (1.f + expf(-(ir + hr)));
        float z = 1.f / (1.f + expf(-(iz + hz)));
        float n = tanhf(in_ + r * hn);
        float hv = (1.f - z) * n + z * hprev[k];
        hnew[k] = hv;
        out_hidden[k] = hv;
    }
}

// ---------------- K3: v = Wa^T @ h1   (grid: (4,16), block 256)
__global__ void k3_v(const float* __restrict__ Wa) {
    const int k  = blockIdx.x * 256 + threadIdx.x;  // column
    const int j0 = blockIdx.y * 64;                 // row tile
    __shared__ float sh[64];
    if (threadIdx.x < 64) sh[threadIdx.x] = g_h1[j0 + threadIdx.x];
    __syncthreads();
    float acc = 0.f;
    #pragma unroll 8
    for (int j = 0; j < 64; j++)
        acc += Wa[(size_t)(j0 + j) * H + k] * sh[j];
    atomicAdd(&g_v[k], acc);
}

// ---------------- K4: scores[s] = enc[s] . v   (grid S, block 256)
__global__ void k4_scores(const float* __restrict__ enc) {
    const int s = blockIdx.x, t = threadIdx.x;
    const float4* e4 = (const float4*)(enc + (size_t)s * H);
    const float4* v4 = (const float4*)g_v;
    float4 a = e4[t], b = v4[t];
    float acc = a.x*b.x + a.y*b.y + a.z*b.z + a.w*b.w;
    __shared__ float red[8];
    int w = t >> 5, lane = t & 31;
    float r = warp_sum(acc);
    if (lane == 0) red[w] = r;
    __syncthreads();
    if (t == 0) {
        float tot = 0.f;
        #pragma unroll
        for (int j = 0; j < 8; j++) tot += red[j];
        g_scores[s] = tot;
    }
}

// ---------------- K5: softmax over S=2048 (1 block, 1024 threads)
__global__ void k5_softmax(float* __restrict__ out_attn) {
    const int t = threadIdx.x;
    float a0 = g_scores[t], a1 = g_scores[t + 1024];
    float m = fmaxf(a0, a1);
    __shared__ float red[32];
    __shared__ float sM, sInv;
    int w = t >> 5, lane = t & 31;
    float r = warp_max(m);
    if (lane == 0) red[w] = r;
    __syncthreads();
    if (t == 0) {
        float M = -INFINITY;
        #pragma unroll
        for (int j = 0; j < 32; j++) M = fmaxf(M, red[j]);
        sM = M;
    }
    __syncthreads();
    float M = sM;
    float e0 = expf(a0 - M), e1 = expf(a1 - M);
    float sum = warp_sum(e0 + e1);
    if (lane == 0) red[w] = sum;
    __syncthreads();
    if (t == 0) {
        float Ssum = 0.f;
        #pragma unroll
        for (int j = 0; j < 32; j++) Ssum += red[j];
        sInv = 1.f / Ssum;
    }
    __syncthreads();
    float inv = sInv;
    float w0 = e0 * inv, w1 = e1 * inv;
    g_attn[t] = w0;        g_attn[t + 1024] = w1;
    out_attn[t] = w0;      out_attn[t + 1024] = w1;
}

// ---------------- K6: context[k] = sum_s attn[s]*enc[s,k]  (grid (4,32), block 256)
__global__ void k6_context(const float* __restrict__ enc) {
    const int k  = blockIdx.x * 256 + threadIdx.x;
    const int s0 = blockIdx.y * 64;
    __shared__ float sh[64];
    if (threadIdx.x < 64) sh[threadIdx.x] = g_attn[s0 + threadIdx.x];
    __syncthreads();
    float acc = 0.f;
    #pragma unroll 8
    for (int j = 0; j < 64; j++)
        acc += sh[j] * enc[(size_t)(s0 + j) * H + k];
    atomicAdd(&g_context[k], acc);
}

// ---------------- K7: logits (warp-per-row, 8 rows/block) + block max/sumexp
__global__ void k7_logits(const float* __restrict__ Wout,
                          const float* __restrict__ bout,
                          float* __restrict__ out_ctx) {
    const int t = threadIdx.x;               // 256
    __shared__ float qs[2*H];
    for (int i = t; i < H; i += 256) {
        qs[i]     = g_h1[i];
        qs[H + i] = g_context[i];
    }
    __syncthreads();
    if (blockIdx.x == 0) {
        for (int i = t; i < H; i += 256) out_ctx[i] = qs[H + i];
    }
    const int w = t >> 5, lane = t & 31;
    const int r = blockIdx.x * 8 + w;
    __shared__ float blog[8];
    float logit = -INFINITY;
    if (r < V) {
        const float4* wr = (const float4*)(Wout + (size_t)r * (2*H));
        const float4* q4 = (const float4*)qs;
        float acc = 0.f;
        #pragma unroll
        for (int i = 0; i < 16; i++) {
            float4 a = wr[lane + i * 32];
            float4 b = q4[lane + i * 32];
            acc += a.x*b.x + a.y*b.y + a.z*b.z + a.w*b.w;
        }
        acc = warp_sum(acc);
        if (lane == 0) {
            logit = acc + bout[r];
            g_logits[r] = logit;
        }
    }
    if (lane == 0) blog[w] = logit;
    __syncthreads();
    if (t == 0) {
        float m = -INFINITY;
        #pragma unroll
        for (int j = 0; j < 8; j++) m = fmaxf(m, blog[j]);
        float s = 0.f;
        #pragma unroll
        for (int j = 0; j < 8; j++)
            if (blog[j] > -INFINITY) s += expf(blog[j] - m);
        g_pm[blockIdx.x] = m;
        g_ps[blockIdx.x] = s;
    }
}

// ---------------- K8: combine partials -> global M, logS (1 block, 1024 threads)
__global__ void k8_combine() {
    const int t = threadIdx.x;
    __shared__ float red[32];
    __shared__ float sM;
    int w = t >> 5, lane = t & 31;
    float m = -INFINITY;
    for (int i = t; i < NB_LOG; i += 1024) m = fmaxf(m, g_pm[i]);
    m = warp_max(m);
    if (lane == 0) red[w] = m;
    __syncthreads();
    if (t == 0) {
        float M = -INFINITY;
        #pragma unroll
        for (int j = 0; j < 32; j++) M = fmaxf(M, red[j]);
        sM = M;
    }
    __syncthreads();
    float M = sM;
    float s = 0.f;
    for (int i = t; i < NB_LOG; i += 1024) s += g_ps[i] * expf(g_pm[i] - M);
    s = warp_sum(s);
    if (lane == 0) red[w] = s;
    __syncthreads();
    if (t == 0) {
        float Ssum = 0.f;
        #pragma unroll
        for (int j = 0; j < 32; j++) Ssum += red[j];
        g_M = M;
        g_logS = logf(Ssum);
    }
}

// ---------------- K9: out[v] = logits[v] - M - logS
__global__ void k9_final(float* __restrict__ out) {
    int v = blockIdx.x * 256 + threadIdx.x;
    if (v < V) out[v] = g_logits[v] - g_M - g_logS;
}

extern "C" void kernel_launch(void* const* d_in, const int* in_sizes, int n_in,
                              void* d_out, int out_size) {
    const int*   word     = (const int*)  d_in[0];
    const float* last_ctx = (const float*)d_in[1];
    const float* last_hid = (const float*)d_in[2];   // [2, H]
    const float* enc      = (const float*)d_in[3];   // [S, H]
    const float* emb      = (const float*)d_in[4];
    const float* W_ih0    = (const float*)d_in[5];
    const float* W_hh0    = (const float*)d_in[6];
    const float* b_ih0    = (const float*)d_in[7];
    const float* b_hh0    = (const float*)d_in[8];
    const float* W_ih1    = (const float*)d_in[9];
    const float* W_hh1    = (const float*)d_in[10];
    const float* b_ih1    = (const float*)d_in[11];
    const float* b_hh1    = (const float*)d_in[12];
    const float* Wa       = (const float*)d_in[13];
    // d_in[14] = ba  (cancels under softmax shift-invariance)
    const float* W_out    = (const float*)d_in[15];
    const float* b_out    = (const float*)d_in[16];
    float* out = (float*)d_out;

    float *g_h0_p, *g_h1_p;
    cudaGetSymbolAddress((void**)&g_h0_p, g_h0);
    cudaGetSymbolAddress((void**)&g_h1_p, g_h1);
    float *g_x_p;
    cudaGetSymbolAddress((void**)&g_x_p, g_x);

    k0_build<<<1, 1024>>>(word, emb, last_ctx);
    k_gru<<<H, 256>>>(g_x_p, 2*H, last_hid,          W_ih0, W_hh0, b_ih0, b_hh0,
                      g_h0_p, out + OUT_HID);
    k_gru<<<H, 256>>>(g_h0_p, H,  last_hid + H,      W_ih1, W_hh1, b_ih1, b_hh1,
                      g_h1_p, out + OUT_HID + H);
    k3_v<<<dim3(4, 16), 256>>>(Wa);
    k4_scores<<<S, 256>>>(enc);
    k5_softmax<<<1, 1024>>>(out + OUT_ATTN);
    k6_context<<<dim3(4, 32), 256>>>(enc);
    k7_logits<<<NB_LOG, 256>>>(W_out, b_out, out + OUT_CTX);
    k8_combine<<<1, 1024>>>();
    k9_final<<<(V + 255) / 256, 256>>>(out);
}

// round 2
// speedup vs baseline: 1.0571x; 1.0571x over previous
#include <cuda_runtime.h>
#include <math.h>

#define V 50257
#define H 1024
#define S 2048
#define NB_LOG 6283   // ceil(V/8)

// out layout: [0,V) log_softmax | [V,V+H) context | [V+H,V+3H) hidden(h0,h1) | [V+3H,V+3H+S) attn
#define OUT_CTX  (V)
#define OUT_HID  (V + H)
#define OUT_ATTN (V + 3*H)

__device__ float g_h0[H];
__device__ float g_h1[H];
__device__ float g_v[H];          // Wa^T @ h1
__device__ float g_scores[S];
__device__ float g_attn[S];
__device__ float g_context[H];
__device__ float g_logits[V];
__device__ float g_pm[NB_LOG];
__device__ float g_ps[NB_LOG];
__device__ float g_M, g_logS;

__device__ __forceinline__ float warp_sum(float v) {
    #pragma unroll
    for (int o = 16; o; o >>= 1) v += __shfl_down_sync(0xffffffffu, v, o);
    return v;
}
__device__ __forceinline__ float warp_max(float v) {
    #pragma unroll
    for (int o = 16; o; o >>= 1) v = fmaxf(v, __shfl_down_sync(0xffffffffu, v, o));
    return v;
}
__device__ __forceinline__ float dot4(float4 a, float4 b) {
    return a.x*b.x + a.y*b.y + a.z*b.z + a.w*b.w;
}

// ---------------- GRU cell. Block k computes h_new[k]. 256 threads.
// SPLIT: x = [emb[word[0]], xb]  (xdim = 2H).  !SPLIT: x = xdirect (xdim = H).
template<bool SPLIT>
__global__ void k_gru(const int* __restrict__ word,
                      const float* __restrict__ emb,
                      const float* __restrict__ xb,
                      const float* __restrict__ xdirect,
                      const float* __restrict__ hprev,
                      const float* __restrict__ Wih,
                      const float* __restrict__ Whh,
                      const float* __restrict__ bih,
                      const float* __restrict__ bhh,
                      float* __restrict__ hnew,
                      float* __restrict__ out_hidden,
                      int zero_v) {
    const int k = blockIdx.x;                  // 0..H-1
    const int t = threadIdx.x;                 // 256
    if (zero_v && t == 0) g_v[k] = 0.f;        // pre-zero for k3's atomics

    const int XDIM = SPLIT ? 2*H : H;
    float acc[6];

    const float4* xa4 = nullptr;
    const float4* xb4 = nullptr;
    const float4* xd4 = nullptr;
    if (SPLIT) {
        int wi = word[0];
        xa4 = (const float4*)(emb + (size_t)wi * H);
        xb4 = (const float4*)xb;
    } else {
        xd4 = (const float4*)xdirect;
    }
    const float4* h4 = (const float4*)hprev;

    #pragma unroll
    for (int g = 0; g < 3; g++) {
        const float* wrow = Wih + (size_t)(g * H + k) * XDIM;
        float a;
        if (SPLIT) {
            a  = dot4(((const float4*)wrow)[t],        xa4[t]);
            a += dot4(((const float4*)(wrow + H))[t],  xb4[t]);
        } else {
            a  = dot4(((const float4*)wrow)[t],        xd4[t]);
        }
        acc[g] = a;
    }
    #pragma unroll
    for (int g = 0; g < 3; g++) {
        const float* wrow = Whh + (size_t)(g * H + k) * H;
        acc[3 + g] = dot4(((const float4*)wrow)[t], h4[t]);
    }

    __shared__ float red[6][8];
    int w = t >> 5, lane = t & 31;
    #pragma unroll
    for (int g = 0; g < 6; g++) {
        float s = warp_sum(acc[g]);
        if (lane == 0) red[g][w] = s;
    }
    __syncthreads();
    if (t == 0) {
        float s[6];
        #pragma unroll
        for (int g = 0; g < 6; g++) {
            float a = 0.f;
            #pragma unroll
            for (int j = 0; j < 8; j++) a += red[g][j];
            s[g] = a;
        }
        float ir = s[0] + bih[k],       hr = s[3] + bhh[k];
        float iz = s[1] + bih[H + k],   hz = s[4] + bhh[H + k];
        float in_= s[2] + bih[2*H + k], hn = s[5] + bhh[2*H + k];
        float r = 1.f / (1.f + expf(-(ir + hr)));
        float z = 1.f / (1.f + expf(-(iz + hz)));
        float n = tanhf(in_ + r * hn);
        float hv = (1.f - z) * n + z * hprev[k];
        hnew[k] = hv;
        out_hidden[k] = hv;
    }
}

// ---------------- K3: v = Wa^T @ h1   (grid (4,64), block 256; 16 rows/block)
__global__ void k3_v(const float* __restrict__ Wa) {
    const int k  = blockIdx.x * 256 + threadIdx.x;
    const int j0 = blockIdx.y * 16;
    __shared__ float sh[16];
    if (threadIdx.x < 16) sh[threadIdx.x] = g_h1[j0 + threadIdx.x];
    __syncthreads();
    float acc = 0.f;
    #pragma unroll
    for (int j = 0; j < 16; j++)
        acc += Wa[(size_t)(j0 + j) * H + k] * sh[j];
    atomicAdd(&g_v[k], acc);
}

// ---------------- K4: scores[s] = enc[s].v  (warp per row, 8 rows/block, grid 256)
__global__ void k4_scores(const float* __restrict__ enc) {
    const int w = threadIdx.x >> 5, lane = threadIdx.x & 31;
    const int s = blockIdx.x * 8 + w;
    const float4* e4 = (const float4*)(enc + (size_t)s * H);
    const float4* v4 = (const float4*)g_v;
    float acc = 0.f;
    #pragma unroll
    for (int i = 0; i < 8; i++)
        acc += dot4(e4[lane + 32*i], v4[lane + 32*i]);
    acc = warp_sum(acc);
    if (lane == 0) g_scores[s] = acc;
}

// ---------------- K5: softmax over S=2048 (1 block, 1024 threads); zero g_context
__global__ void k5_softmax(float* __restrict__ out_attn) {
    const int t = threadIdx.x;
    g_context[t] = 0.f;                       // pre-zero for k6's atomics
    float a0 = g_scores[t], a1 = g_scores[t + 1024];
    float m = fmaxf(a0, a1);
    __shared__ float red[32];
    __shared__ float sM, sInv;
    int w = t >> 5, lane = t & 31;
    float r = warp_max(m);
    if (lane == 0) red[w] = r;
    __syncthreads();
    if (t == 0) {
        float M = -INFINITY;
        #pragma unroll
        for (int j = 0; j < 32; j++) M = fmaxf(M, red[j]);
        sM = M;
    }
    __syncthreads();
    float M = sM;
    float e0 = expf(a0 - M), e1 = expf(a1 - M);
    float sum = warp_sum(e0 + e1);
    if (lane == 0) red[w] = sum;
    __syncthreads();
    if (t == 0) {
        float Ssum = 0.f;
        #pragma unroll
        for (int j = 0; j < 32; j++) Ssum += red[j];
        sInv = 1.f / Ssum;
    }
    __syncthreads();
    float inv = sInv;
    float w0 = e0 * inv, w1 = e1 * inv;
    g_attn[t] = w0;        g_attn[t + 1024] = w1;
    out_attn[t] = w0;      out_attn[t + 1024] = w1;
}

// ---------------- K6: context[k] += sum_s attn[s]*enc[s,k]  (grid (4,128), 16 s/block)
__global__ void k6_context(const float* __restrict__ enc) {
    const int k  = blockIdx.x * 256 + threadIdx.x;
    const int s0 = blockIdx.y * 16;
    __shared__ float sh[16];
    if (threadIdx.x < 16) sh[threadIdx.x] = g_attn[s0 + threadIdx.x];
    __syncthreads();
    float acc = 0.f;
    #pragma unroll
    for (int j = 0; j < 16; j++)
        acc += sh[j] * enc[(size_t)(s0 + j) * H + k];
    atomicAdd(&g_context[k], acc);
}

// ---------------- K7: logits (warp-per-row, 8 rows/block) + block max/sumexp
__global__ void k7_logits(const float* __restrict__ Wout,
                          const float* __restrict__ bout,
                          float* __restrict__ out_ctx) {
    const int t = threadIdx.x;               // 256
    __shared__ float qs[2*H];
    for (int i = t; i < H; i += 256) {
        qs[i]     = g_h1[i];
        qs[H + i] = g_context[i];
    }
    __syncthreads();
    if (blockIdx.x == 0) {
        for (int i = t; i < H; i += 256) out_ctx[i] = qs[H + i];
    }
    const int w = t >> 5, lane = t & 31;
    const int r = blockIdx.x * 8 + w;
    __shared__ float blog[8];
    float logit = -INFINITY;
    if (r < V) {
        const float4* wr = (const float4*)(Wout + (size_t)r * (2*H));
        const float4* q4 = (const float4*)qs;
        float acc0 = 0.f, acc1 = 0.f;
        #pragma unroll
        for (int i = 0; i < 16; i += 2) {
            acc0 += dot4(wr[lane + i*32],       q4[lane + i*32]);
            acc1 += dot4(wr[lane + (i+1)*32],   q4[lane + (i+1)*32]);
        }
        float acc = warp_sum(acc0 + acc1);
        if (lane == 0) {
            logit = acc + bout[r];
            g_logits[r] = logit;
        }
    }
    if (lane == 0) blog[w] = logit;
    __syncthreads();
    if (t == 0) {
        float m = -INFINITY;
        #pragma unroll
        for (int j = 0; j < 8; j++) m = fmaxf(m, blog[j]);
        float s = 0.f;
        #pragma unroll
        for (int j = 0; j < 8; j++)
            if (blog[j] > -INFINITY) s += expf(blog[j] - m);
        g_pm[blockIdx.x] = m;
        g_ps[blockIdx.x] = s;
    }
}

// ---------------- K8: combine partials -> global M, logS (1 block, 1024 threads)
__global__ void k8_combine() {
    const int t = threadIdx.x;
    __shared__ float red[32];
    __shared__ float sM;
    int w = t >> 5, lane = t & 31;
    float m = -INFINITY;
    for (int i = t; i < NB_LOG; i += 1024) m = fmaxf(m, g_pm[i]);
    m = warp_max(m);
    if (lane == 0) red[w] = m;
    __syncthreads();
    if (t == 0) {
        float M = -INFINITY;
        #pragma unroll
        for (int j = 0; j < 32; j++) M = fmaxf(M, red[j]);
        sM = M;
    }
    __syncthreads();
    float M = sM;
    float s = 0.f;
    for (int i = t; i < NB_LOG; i += 1024) s += g_ps[i] * expf(g_pm[i] - M);
    s = warp_sum(s);
    if (lane == 0) red[w] = s;
    __syncthreads();
    if (t == 0) {
        float Ssum = 0.f;
        #pragma unroll
        for (int j = 0; j < 32; j++) Ssum += red[j];
        g_M = M;
        g_logS = logf(Ssum);
    }
}

// ---------------- K9: out[v] = logits[v] - M - logS
__global__ void k9_final(float* __restrict__ out) {
    int v = blockIdx.x * 256 + threadIdx.x;
    if (v < V) out[v] = g_logits[v] - g_M - g_logS;
}

extern "C" void kernel_launch(void* const* d_in, const int* in_sizes, int n_in,
                              void* d_out, int out_size) {
    const int*   word     = (const int*)  d_in[0];
    const float* last_ctx = (const float*)d_in[1];
    const float* last_hid = (const float*)d_in[2];   // [2, H]
    const float* enc      = (const float*)d_in[3];   // [S, H]
    const float* emb      = (const float*)d_in[4];
    const float* W_ih0    = (const float*)d_in[5];
    const float* W_hh0    = (const float*)d_in[6];
    const float* b_ih0    = (const float*)d_in[7];
    const float* b_hh0    = (const float*)d_in[8];
    const float* W_ih1    = (const float*)d_in[9];
    const float* W_hh1    = (const float*)d_in[10];
    const float* b_ih1    = (const float*)d_in[11];
    const float* b_hh1    = (const float*)d_in[12];
    const float* Wa       = (const float*)d_in[13];
    // d_in[14] = ba  (cancels under softmax shift-invariance)
    const float* W_out    = (const float*)d_in[15];
    const float* b_out    = (const float*)d_in[16];
    float* out = (float*)d_out;

    float *g_h0_p, *g_h1_p;
    cudaGetSymbolAddress((void**)&g_h0_p, g_h0);
    cudaGetSymbolAddress((void**)&g_h1_p, g_h1);

    k_gru<true ><<<H, 256>>>(word, emb, last_ctx, nullptr, last_hid,
                             W_ih0, W_hh0, b_ih0, b_hh0,
                             g_h0_p, out + OUT_HID, 0);
    k_gru<false><<<H, 256>>>(nullptr, nullptr, nullptr, g_h0_p, last_hid + H,
                             W_ih1, W_hh1, b_ih1, b_hh1,
                             g_h1_p, out + OUT_HID + H, 1);
    k3_v<<<dim3(4, 64), 256>>>(Wa);
    k4_scores<<<256, 256>>>(enc);
    k5_softmax<<<1, 1024>>>(out + OUT_ATTN);
    k6_context<<<dim3(4, 128), 256>>>(enc);
    k7_logits<<<NB_LOG, 256>>>(W_out, b_out, out + OUT_CTX);
    k8_combine<<<1, 1024>>>();
    k9_final<<<(V + 255) / 256, 256>>>(out);
}